// round 4
// baseline (speedup 1.0000x reference)
#include <cuda_runtime.h>

#define NCLS 16
#define MTOT (8*512*512)       // 2097152 pixels
#define CHST (512*512)         // channel stride in cls_score
#define LOG_EPS (-4.6051701859880914f)   // log(0.01)

__device__ int    g_hist[NCLS];
__device__ double g_nll;
__device__ float  g_logcum[NCLS];

// ---------------- init ----------------
__global__ void k_init() {
    int t = threadIdx.x;
    if (t < NCLS) g_hist[t] = 0;
    if (t == 0)   g_nll = 0.0;
}

// ---------------- histogram (ballot-based, no hot atomics) ----------------
// grid*block chosen so MTOT % (grid*block) == 0 -> every lane does identical
// iteration count -> ballots are never divergent.
__global__ void k_hist(const int* __restrict__ labels) {
    __shared__ int sh[NCLS];
    int t = threadIdx.x;
    if (t < NCLS) sh[t] = 0;
    __syncthreads();

    int lane   = t & 31;
    unsigned cnt = 0;
    int idx    = blockIdx.x * blockDim.x + t;
    int stride = gridDim.x * blockDim.x;
    for (int i = idx; i < MTOT; i += stride) {
        int lab = labels[i];
#pragma unroll
        for (int c = 0; c < NCLS; c++) {
            unsigned b = __ballot_sync(0xffffffffu, lab == c);
            if (lane == c) cnt += __popc(b);
        }
    }
    if (lane < NCLS) atomicAdd(&sh[lane], (int)cnt);
    __syncthreads();
    if (t < NCLS) atomicAdd(&g_hist[t], sh[t]);
}

// ---------------- prep: log of clipped cumulative counts ----------------
__global__ void k_prep(const float* __restrict__ cum_samples) {
    int t = threadIdx.x;
    if (t < NCLS) {
        float cc = cum_samples[t] + (float)g_hist[t];
        cc = fmaxf(cc, 1.0f);
        g_logcum[t] = logf(cc);
    }
}

// ---------------- main: per-pixel seesaw NLL ----------------
__global__ void __launch_bounds__(256) k_main(const float* __restrict__ score,
                                              const int*   __restrict__ labels) {
    __shared__ float slog[NCLS];
    __shared__ float swarp[8];
    int t = threadIdx.x;
    if (t < NCLS) slog[t] = g_logcum[t];
    __syncthreads();

    float acc = 0.0f;
    int stride = gridDim.x * blockDim.x;
    for (int m = blockIdx.x * blockDim.x + t; m < MTOT; m += stride) {
        int lab = labels[m];
        if (lab == 0) continue;             // ignore_index: no NLL contribution

        int b   = m >> 18;                  // batch (CHST = 2^18)
        int rem = m & (CHST - 1);           // h*512 + w
        const float* base = score + b * (NCLS * CHST) + rem;

        float l[NCLS];
#pragma unroll
        for (int c = 0; c < NCLS; c++) l[c] = __ldg(base + c * CHST);

        // pick l[lab] without dynamic register indexing
        float lL = l[0];
#pragma unroll
        for (int c = 1; c < NCLS; c++) if (lab == c) lL = l[c];

        // pass 1: logsumexp of raw logits
        float mx = l[0];
#pragma unroll
        for (int c = 1; c < NCLS; c++) mx = fmaxf(mx, l[c]);
        float s = 0.0f;
#pragma unroll
        for (int c = 0; c < NCLS; c++) s += __expf(l[c] - mx);
        float lse1 = mx + __logf(s);

        // log-domain seesaw weights
        float slc = fmaxf(lL - lse1, LOG_EPS);   // log(clip(self_score, EPS))
        float off = lse1 + slc;                  // l[c]-off = log(score_mat[c])
        float lcL = slog[lab];

        float mx2 = -1e30f;
#pragma unroll
        for (int c = 0; c < NCLS; c++) {
            // mitigation: 0.8*min(0, log ratio); compensation: 2*max(0, log score_mat)
            float w = 0.8f * fminf(0.0f, slog[c] - lcL)
                    + 2.0f * fmaxf(0.0f, l[c] - off);
            // at c==lab both terms are exactly 0 -> no onehot special case needed
            float a = l[c] + w;
            l[c] = a;
            mx2 = fmaxf(mx2, a);
        }

        // pass 2: logsumexp of adjusted logits; adj[lab] == l_raw[lab]
        float s2 = 0.0f;
#pragma unroll
        for (int c = 0; c < NCLS; c++) s2 += __expf(l[c] - mx2);
        acc += mx2 + __logf(s2) - lL;            // nll
    }

    // block reduction
#pragma unroll
    for (int o = 16; o > 0; o >>= 1) acc += __shfl_xor_sync(0xffffffffu, acc, o);
    int warp = t >> 5, lane = t & 31;
    if (lane == 0) swarp[warp] = acc;
    __syncthreads();
    if (warp == 0) {
        float v = (lane < (int)(blockDim.x >> 5)) ? swarp[lane] : 0.0f;
#pragma unroll
        for (int o = 4; o > 0; o >>= 1) v += __shfl_xor_sync(0xffffffffu, v, o);
        if (lane == 0) atomicAdd(&g_nll, (double)v);
    }
}

// ---------------- finalize ----------------
__global__ void k_fin(float* out) {
    out[0] = (float)(g_nll / (double)(MTOT - g_hist[0]));
}

extern "C" void kernel_launch(void* const* d_in, const int* in_sizes, int n_in,
                              void* d_out, int out_size) {
    const float* cls   = nullptr;
    const int*   lab   = nullptr;
    const float* cums  = nullptr;
    for (int i = 0; i < n_in; i++) {
        if (in_sizes[i] == MTOT * NCLS)      cls  = (const float*)d_in[i];
        else if (in_sizes[i] == MTOT)        lab  = (const int*)d_in[i];
        else if (in_sizes[i] == NCLS)        cums = (const float*)d_in[i];
    }
    if (!cls)  cls  = (const float*)d_in[0];
    if (!lab)  lab  = (const int*)d_in[1];
    if (!cums) cums = (const float*)d_in[2];

    k_init<<<1, 32>>>();
    // 512 blocks * 256 threads = 131072 threads; 2097152 / 131072 = 16 iters exactly
    k_hist<<<512, 256>>>(lab);
    k_prep<<<1, NCLS>>>(cums);
    k_main<<<2048, 256>>>(cls, lab);
    k_fin<<<1, 1>>>((float*)d_out);
    (void)out_size; (void)n_in;
}